// round 17
// baseline (speedup 1.0000x reference)
#include <cuda_runtime.h>
#include <cuda_fp16.h>
#include <math.h>
#include <stdint.h>

// ----------------------------------------------------------------------------
// Problem constants
// ----------------------------------------------------------------------------
#define B      2
#define N_SEQ  2048
#define DIM    2048
#define HEADS  16
#define DHEAD  128
#define INNER  (HEADS * DHEAD)       // 2048
#define ROWS   (B * N_SEQ)           // 4096
#define NQKV   (3 * INNER)           // 6144

// ----------------------------------------------------------------------------
// Scratch (device globals; no allocations allowed)
// ----------------------------------------------------------------------------
__device__ __half g_xn  [ROWS * DIM];
__device__ __half g_qkv [ROWS * NQKV];
__device__ __half g_o   [ROWS * INNER];
__device__ __half g_wqkv[DIM * NQKV];
__device__ __half g_wo  [INNER * DIM];
__device__ float  g_cos [N_SEQ * DHEAD];
__device__ float  g_sin [N_SEQ * DHEAD];

// ----------------------------------------------------------------------------
// helpers
// ----------------------------------------------------------------------------
__device__ __forceinline__ uint32_t f2h2(float lo, float hi) {
    uint32_t r;
    asm("cvt.rn.f16x2.f32 %0, %1, %2;" : "=r"(r) : "f"(hi), "f"(lo));
    return r;
}

__device__ __forceinline__ uint32_t hmul2(uint32_t a, uint32_t b) {
    uint32_t r;
    asm("mul.rn.f16x2 %0, %1, %2;" : "=r"(r) : "r"(a), "r"(b));
    return r;
}

__device__ __forceinline__ float fex2(float x) {
    float y;
    asm("ex2.approx.ftz.f32 %0, %1;" : "=f"(y) : "f"(x));
    return y;
}

__device__ __forceinline__ void mma_f16(float* c, const uint32_t* a, const uint32_t* b) {
    asm volatile(
        "mma.sync.aligned.m16n8k16.row.col.f32.f16.f16.f32 "
        "{%0,%1,%2,%3},{%4,%5,%6,%7},{%8,%9},{%0,%1,%2,%3};"
        : "+f"(c[0]), "+f"(c[1]), "+f"(c[2]), "+f"(c[3])
        : "r"(a[0]), "r"(a[1]), "r"(a[2]), "r"(a[3]), "r"(b[0]), "r"(b[1]));
}

__device__ __forceinline__ void ldm_x4(uint32_t* d, uint32_t addr) {
    asm volatile("ldmatrix.sync.aligned.m8n8.x4.shared.b16 {%0,%1,%2,%3}, [%4];"
                 : "=r"(d[0]), "=r"(d[1]), "=r"(d[2]), "=r"(d[3]) : "r"(addr));
}
__device__ __forceinline__ void ldm_x4_t(uint32_t* d, uint32_t addr) {
    asm volatile("ldmatrix.sync.aligned.m8n8.x4.trans.shared.b16 {%0,%1,%2,%3}, [%4];"
                 : "=r"(d[0]), "=r"(d[1]), "=r"(d[2]), "=r"(d[3]) : "r"(addr));
}

__device__ __forceinline__ uint32_t smem_u32(const void* p) {
    uint32_t a;
    asm("{ .reg .u64 t; cvta.to.shared.u64 t, %1; cvt.u32.u64 %0, t; }"
        : "=r"(a) : "l"(p));
    return a;
}

__device__ __forceinline__ void cpa16(uint32_t saddr, const void* g) {
    asm volatile("cp.async.cg.shared.global [%0], [%1], 16;" :: "r"(saddr), "l"(g));
}
#define CPA_COMMIT() asm volatile("cp.async.commit_group;" ::: "memory")
#define CPA_WAIT0()  asm volatile("cp.async.wait_group 0;"  ::: "memory")

// ----------------------------------------------------------------------------
// Fused setup: Wq|Wkv|Wo fp32->fp16 (with remap) + cos/sin tables, one launch.
// ----------------------------------------------------------------------------
#define SU_N0 (DIM * INNER / 4)
#define SU_N1 (DIM * 2 * INNER / 4)
#define SU_N2 (INNER * DIM / 4)
#define SU_N3 (N_SEQ * DHEAD / 4)
#define SU_TOTAL (SU_N0 + SU_N1 + SU_N2 + SU_N3)

__global__ __launch_bounds__(256) void setup_kernel(
    const float* __restrict__ Wq, const float* __restrict__ Wkv,
    const float* __restrict__ Wo, const float* __restrict__ re,
    __half* __restrict__ wqkv, __half* __restrict__ wo,
    float* __restrict__ ct, float* __restrict__ st)
{
    int idx = blockIdx.x * 256 + threadIdx.x;
    if (idx < SU_N0) {
        const int e = idx * 4;
        const int r = e / INNER, c = e - r * INNER;
        float4 v = *(const float4*)(Wq + e);
        *(uint2*)(wqkv + (size_t)r * NQKV + c) =
            make_uint2(f2h2(v.x, v.y), f2h2(v.z, v.w));
        return;
    }
    idx -= SU_N0;
    if (idx < SU_N1) {
        const int e = idx * 4;
        const int r = e / (2 * INNER), c = e - r * (2 * INNER);
        float4 v = *(const float4*)(Wkv + e);
        *(uint2*)(wqkv + (size_t)r * NQKV + INNER + c) =
            make_uint2(f2h2(v.x, v.y), f2h2(v.z, v.w));
        return;
    }
    idx -= SU_N1;
    if (idx < SU_N2) {
        const int e = idx * 4;
        float4 v = *(const float4*)(Wo + e);
        *(uint2*)(wo + e) = make_uint2(f2h2(v.x, v.y), f2h2(v.z, v.w));
        return;
    }
    idx -= SU_N2;
    if (idx < SU_N3) {
        const int e = idx * 4;
        float4 p = *(const float4*)(re + e);
        *(float4*)(ct + e) = make_float4(cosf(p.x), cosf(p.y), cosf(p.z), cosf(p.w));
        *(float4*)(st + e) = make_float4(sinf(p.x), sinf(p.y), sinf(p.z), sinf(p.w));
    }
}

// ----------------------------------------------------------------------------
// RMSNorm -> fp16 output (float4 path)
// ----------------------------------------------------------------------------
__global__ __launch_bounds__(256) void rmsnorm_kernel(
    const float* __restrict__ x, const float* __restrict__ g,
    __half* __restrict__ xn)
{
    const int row = blockIdx.x;
    const float* xr = x  + (size_t)row * DIM;
    __half*      xo = xn + (size_t)row * DIM;

    float ss = 0.f;
    #pragma unroll
    for (int i = threadIdx.x * 4; i < DIM; i += 1024) {
        float4 v = *(const float4*)(xr + i);
        ss += v.x * v.x + v.y * v.y + v.z * v.z + v.w * v.w;
    }
    __shared__ float red[8];
    #pragma unroll
    for (int o = 16; o > 0; o >>= 1) ss += __shfl_xor_sync(0xffffffffu, ss, o);
    if ((threadIdx.x & 31) == 0) red[threadIdx.x >> 5] = ss;
    __syncthreads();
    if (threadIdx.x < 8) {
        float v = red[threadIdx.x];
        #pragma unroll
        for (int o = 4; o > 0; o >>= 1) v += __shfl_xor_sync(0x000000ffu, v, o);
        if (threadIdx.x == 0) red[0] = v;
    }
    __syncthreads();
    const float rms = sqrtf(red[0] * (1.f / (float)DIM));
    const float inv = 1.f / fmaxf(rms, 1e-8f);
    #pragma unroll
    for (int i = threadIdx.x * 4; i < DIM; i += 1024) {
        float4 v = *(const float4*)(xr + i);
        float4 gg = *(const float4*)(g + i);
        *(uint2*)(xo + i) = make_uint2(
            f2h2(v.x * inv * gg.x, v.y * inv * gg.y),
            f2h2(v.z * inv * gg.z, v.w * inv * gg.w));
    }
}

// ----------------------------------------------------------------------------
// FP16 tensor-core GEMM (m16n8k16), cp.async double-buffered, ldmatrix.
// Optional fused RoPE epilogue for q/k block-columns (ROPE && blockIdx.x < 32):
// acc -> fp16 smem tile (aliasing dead pipeline buffers) -> partner exchange
// -> fp32 rope with tables -> fp16 store. Bit-identical to the separate pass.
// ----------------------------------------------------------------------------
#define G_BK 32
#define G_SA 40
#define G_SB 136
#define G_ABUF (128 * G_SA * 2)
#define G_BBUF (G_BK * G_SB * 2)
#define G_SMEMB (2 * G_ABUF + 2 * G_BBUF)   // 37888 bytes
#define G_ES 136                            // rope exchange tile stride (halfs)

template <typename OutT, bool ROPE>
__global__ __launch_bounds__(256, 2) void h16_gemm_kernel(
    int M, int N, int K,
    const __half* __restrict__ A, const __half* __restrict__ Bm,
    OutT* __restrict__ C,
    const float* __restrict__ ct, const float* __restrict__ st)
{
    __shared__ __align__(16) char smraw[G_SMEMB];

    const int tid  = threadIdx.x;
    const int lane = tid & 31;
    const int warp = tid >> 5;
    const int mbase = (warp >> 1) * 32;
    const int nbase = (warp & 1) * 64;

    const int aRow = tid >> 1;
    const int aCol = (tid & 1) * 16;
    const int bRow = tid >> 4;
    const int bCol = (tid & 15) * 8;

    const __half* Ap = A  + (size_t)blockIdx.y * 128 * K;
    const __half* Bp = Bm + (size_t)blockIdx.x * 128;

    const uint32_t asBase = smem_u32(smraw);
    const uint32_t bsBase = asBase + 2 * G_ABUF;
    const uint32_t aDst = asBase + (uint32_t)(aRow * G_SA + aCol) * 2;
    const uint32_t bDst0 = bsBase + (uint32_t)(bRow * G_SB + bCol) * 2;
    const uint32_t bDst1 = bsBase + (uint32_t)((bRow + 16) * G_SB + bCol) * 2;
    const int lrow = lane & 15;
    const int lcb  = (lane >> 4) << 3;

    {
        const __half* Ar = Ap + (size_t)aRow * K + aCol;
        cpa16(aDst,      Ar);
        cpa16(aDst + 16, Ar + 8);
        cpa16(bDst0, Bp + (size_t)bRow        * N + bCol);
        cpa16(bDst1, Bp + (size_t)(bRow + 16) * N + bCol);
        CPA_COMMIT();
    }
    CPA_WAIT0();
    __syncthreads();

    float acc[2][8][4];
    #pragma unroll
    for (int mi = 0; mi < 2; mi++)
        #pragma unroll
        for (int ni = 0; ni < 8; ni++)
            #pragma unroll
            for (int e = 0; e < 4; e++) acc[mi][ni][e] = 0.f;

    const int nT = K / G_BK;
    for (int t = 0; t < nT; t++) {
        const int cur = t & 1;

        if (t + 1 < nT) {
            const uint32_t boff = (uint32_t)((t + 1) & 1);
            const __half* Ar = Ap + (size_t)aRow * K + (t + 1) * G_BK + aCol;
            cpa16(aDst + boff * G_ABUF,      Ar);
            cpa16(aDst + boff * G_ABUF + 16, Ar + 8);
            const __half* Br = Bp + (size_t)((t + 1) * G_BK) * N;
            cpa16(bDst0 + boff * G_BBUF, Br + (size_t)bRow        * N + bCol);
            cpa16(bDst1 + boff * G_BBUF, Br + (size_t)(bRow + 16) * N + bCol);
            CPA_COMMIT();
        }

        const uint32_t asB = asBase + (uint32_t)cur * G_ABUF;
        const uint32_t bsB = bsBase + (uint32_t)cur * G_BBUF;
        #pragma unroll
        for (int ks = 0; ks < G_BK; ks += 16) {
            uint32_t af[2][4];
            ldm_x4(af[0], asB + (uint32_t)((mbase      + lrow) * G_SA + ks + lcb) * 2);
            ldm_x4(af[1], asB + (uint32_t)((mbase + 16 + lrow) * G_SA + ks + lcb) * 2);
            uint32_t bf[8][2];
            #pragma unroll
            for (int nb = 0; nb < 4; nb++) {
                uint32_t td[4];
                ldm_x4_t(td, bsB + (uint32_t)((ks + lrow) * G_SB + nbase + nb * 16 + lcb) * 2);
                bf[2 * nb][0]     = td[0];
                bf[2 * nb][1]     = td[1];
                bf[2 * nb + 1][0] = td[2];
                bf[2 * nb + 1][1] = td[3];
            }
            #pragma unroll
            for (int mi = 0; mi < 2; mi++)
                #pragma unroll
                for (int ni = 0; ni < 8; ni++)
                    mma_f16(acc[mi][ni], af[mi], bf[ni]);
        }

        if (t + 1 < nT) CPA_WAIT0();
        __syncthreads();
    }

    const bool do_rope = ROPE && (blockIdx.x < 32);

    if (do_rope) {
        // quantize acc -> fp16 exchange tile (aliases dead pipeline buffers)
        __half* Es = reinterpret_cast<__half*>(smraw);
        #pragma unroll
        for (int mi = 0; mi < 2; mi++) {
            const int r = mbase + mi * 16 + (lane >> 2);
            #pragma unroll
            for (int ni = 0; ni < 8; ni++) {
                const int c = nbase + ni * 8 + (lane & 3) * 2;
                *(uint32_t*)&Es[r * G_ES + c]       = f2h2(acc[mi][ni][0], acc[mi][ni][1]);
                *(uint32_t*)&Es[(r + 8) * G_ES + c] = f2h2(acc[mi][ni][2], acc[mi][ni][3]);
            }
        }
        __syncthreads();
        // partner exchange + fp32 rope + fp16 store (bit-identical to old pass)
        OutT* Cp = C + (size_t)(blockIdx.y * 128) * N + blockIdx.x * 128;
        #pragma unroll
        for (int mi = 0; mi < 2; mi++) {
            #pragma unroll
            for (int rr = 0; rr < 2; rr++) {
                const int r = mbase + mi * 16 + rr * 8 + (lane >> 2);
                const int n = (blockIdx.y * 128 + r) & (N_SEQ - 1);
                #pragma unroll
                for (int ni = 0; ni < 8; ni++) {
                    const int c = nbase + ni * 8 + (lane & 3) * 2;
                    float o0, o1;
                    {
                        const float tv = __half2float(Es[r * G_ES + c]);
                        const float pv = __half2float(Es[r * G_ES + (c ^ 64)]);
                        const float cc1 = ct[n * DHEAD + c];
                        const float ss1 = st[n * DHEAD + c];
                        o0 = (c < 64) ? tv * cc1 - pv * ss1 : tv * cc1 + pv * ss1;
                    }
                    {
                        const int c2 = c + 1;
                        const float tv = __half2float(Es[r * G_ES + c2]);
                        const float pv = __half2float(Es[r * G_ES + (c2 ^ 64)]);
                        const float cc1 = ct[n * DHEAD + c2];
                        const float ss1 = st[n * DHEAD + c2];
                        o1 = (c2 < 64) ? tv * cc1 - pv * ss1 : tv * cc1 + pv * ss1;
                    }
                    *(uint32_t*)((__half*)Cp + (size_t)r * N + c) = f2h2(o0, o1);
                }
            }
        }
        return;
    }

    OutT* Cp = C + (size_t)(blockIdx.y * 128 + mbase) * N + blockIdx.x * 128 + nbase;
    #pragma unroll
    for (int mi = 0; mi < 2; mi++) {
        const int r = mi * 16 + (lane >> 2);
        #pragma unroll
        for (int ni = 0; ni < 8; ni++) {
            const int c = ni * 8 + (lane & 3) * 2;
            if constexpr (sizeof(OutT) == 2) {
                *(uint32_t*)(Cp + (size_t)r       * N + c) = f2h2(acc[mi][ni][0], acc[mi][ni][1]);
                *(uint32_t*)(Cp + (size_t)(r + 8) * N + c) = f2h2(acc[mi][ni][2], acc[mi][ni][3]);
            } else {
                *(float2*)(Cp + (size_t)r       * N + c) = make_float2(acc[mi][ni][0], acc[mi][ni][1]);
                *(float2*)(Cp + (size_t)(r + 8) * N + c) = make_float2(acc[mi][ni][2], acc[mi][ni][3]);
            }
        }
    }
}

// ----------------------------------------------------------------------------
// Causal flash attention, fp16 m16n8k16, cp.async double-buffered KV.
// BM=64, 128 threads (4 warps) -> 2 CTAs/SM.
// ----------------------------------------------------------------------------
#define FA_BM 64
#define FA_BN 64
#define FA_SK 136
#define FA_KVST (2 * FA_BN * FA_SK)
#define FA_SMEM (2 * FA_KVST * 2)

__global__ __launch_bounds__(128, 2) void attn_h16_kernel(
    const __half* __restrict__ QKV, __half* __restrict__ O)
{
    extern __shared__ __half smh[];
    const uint32_t sBase = smem_u32(smh);

    const int bh = blockIdx.y;
    const int b  = bh >> 4;
    const int h  = bh & 15;
    const int qt = gridDim.x - 1 - blockIdx.x;

    const int tid  = threadIdx.x;
    const int lane = tid & 31;
    const int warp = tid >> 5;

    const int cr = tid >> 4;
    const int cc = (tid & 15) * 8;
    const __half* kvb = QKV + ((size_t)(b * N_SEQ)) * NQKV + INNER + h * DHEAD;

    {
        #pragma unroll
        for (int i = 0; i < 8; i++) {
            const int r = i * 8 + cr;
            const uint32_t kD = sBase + (uint32_t)(r * FA_SK + cc) * 2;
            cpa16(kD, kvb + (size_t)r * NQKV + cc);
            cpa16(kD + FA_BN * FA_SK * 2, kvb + (size_t)r * NQKV + INNER + cc);
        }
        CPA_COMMIT();
    }

    const float qsf = 0.088388347648318447f * 1.4426950408889634f;
    const uint32_t qs2 = f2h2(qsf, qsf);
    uint32_t qf[8][4];
    {
        const __half* qb = QKV + ((size_t)(b * N_SEQ + qt * FA_BM + warp * 16 + (lane >> 2))) * NQKV
                               + h * DHEAD;
        #pragma unroll
        for (int ks = 0; ks < 8; ks++) {
            const int k0 = ks * 16 + 2 * (lane & 3);
            qf[ks][0] = hmul2(*(const uint32_t*)(qb + k0), qs2);
            qf[ks][1] = hmul2(*(const uint32_t*)(qb + 8 * NQKV + k0), qs2);
            qf[ks][2] = hmul2(*(const uint32_t*)(qb + k0 + 8), qs2);
            qf[ks][3] = hmul2(*(const uint32_t*)(qb + 8 * NQKV + k0 + 8), qs2);
        }
    }

    float oacc[16][4];
    #pragma unroll
    for (int nd = 0; nd < 16; nd++)
        #pragma unroll
        for (int e = 0; e < 4; e++) oacc[nd][e] = 0.f;

    float m0 = -INFINITY, m1 = -INFINITY, l0 = 0.f, l1 = 0.f;
    const int qrow0 = qt * FA_BM + warp * 16 + (lane >> 2);
    const int warp_min_row = qt * FA_BM + warp * 16;

    CPA_WAIT0();
    __syncthreads();

    const int ntiles = qt + 1;
    for (int kt = 0; kt < ntiles; kt++) {
        const int cur = kt & 1;

        if (kt + 1 < ntiles) {
            const int nxt = cur ^ 1;
            const __half* kvn = kvb + (size_t)((kt + 1) * FA_BN) * NQKV;
            const uint32_t stB = sBase + (uint32_t)nxt * FA_KVST * 2;
            #pragma unroll
            for (int i = 0; i < 8; i++) {
                const int r = i * 8 + cr;
                const uint32_t kD = stB + (uint32_t)(r * FA_SK + cc) * 2;
                cpa16(kD, kvn + (size_t)r * NQKV + cc);
                cpa16(kD + FA_BN * FA_SK * 2, kvn + (size_t)r * NQKV + INNER + cc);
            }
            CPA_COMMIT();
        }

        {
            const uint32_t ksBase = sBase + (uint32_t)cur * FA_KVST * 2;
            const uint32_t vsBase = ksBase + FA_BN * FA_SK * 2;

            float sacc[8][4];
            #pragma unroll
            for (int ni = 0; ni < 8; ni++)
                #pragma unroll
                for (int e = 0; e < 4; e++) sacc[ni][e] = 0.f;

            #pragma unroll
            for (int ks = 0; ks < 8; ks++) {
                uint32_t kf[8][2];
                #pragma unroll
                for (int np = 0; np < 4; np++) {
                    uint32_t td[4];
                    ldm_x4(td, ksBase + (uint32_t)(
                        (np * 16 + (lane & 7) + ((lane >> 4) << 3)) * FA_SK
                        + ks * 16 + (lane & 8)) * 2);
                    kf[2 * np][0]     = td[0];
                    kf[2 * np][1]     = td[1];
                    kf[2 * np + 1][0] = td[2];
                    kf[2 * np + 1][1] = td[3];
                }
                #pragma unroll
                for (int ni = 0; ni < 8; ni++)
                    mma_f16(sacc[ni], qf[ks], kf[ni]);
            }

            if (kt * FA_BN + FA_BN - 1 > warp_min_row) {
                #pragma unroll
                for (int ni = 0; ni < 8; ni++) {
                    const int cg = kt * FA_BN + ni * 8 + 2 * (lane & 3);
                    #pragma unroll
                    for (int e = 0; e < 4; e++) {
                        const int col = cg + (e & 1);
                        const int row = qrow0 + (e >> 1) * 8;
                        if (col > row) sacc[ni][e] = -INFINITY;
                    }
                }
            }

            float rmax0 = -INFINITY, rmax1 = -INFINITY;
            #pragma unroll
            for (int ni = 0; ni < 8; ni++) {
                rmax0 = fmaxf(rmax0, fmaxf(sacc[ni][0], sacc[ni][1]));
                rmax1 = fmaxf(rmax1, fmaxf(sacc[ni][2], sacc[ni][3]));
            }
            rmax0 = fmaxf(rmax0, __shfl_xor_sync(0xffffffffu, rmax0, 1));
            rmax0 = fmaxf(rmax0, __shfl_xor_sync(0xffffffffu, rmax0, 2));
            rmax1 = fmaxf(rmax1, __shfl_xor_sync(0xffffffffu, rmax1, 1));
            rmax1 = fmaxf(rmax1, __shfl_xor_sync(0xffffffffu, rmax1, 2));

            const float mn0 = fmaxf(m0, rmax0);
            const float mn1 = fmaxf(m1, rmax1);
            const float c0 = fex2(m0 - mn0);
            const float c1 = fex2(m1 - mn1);
            float ps0 = 0.f, ps1 = 0.f;
            #pragma unroll
            for (int ni = 0; ni < 8; ni++) {
                sacc[ni][0] = fex2(sacc[ni][0] - mn0);
                sacc[ni][1] = fex2(sacc[ni][1] - mn0);
                sacc[ni][2] = fex2(sacc[ni][2] - mn1);
                sacc[ni][3] = fex2(sacc[ni][3] - mn1);
                ps0 += sacc[ni][0] + sacc[ni][1];
                ps1 += sacc[ni][2] + sacc[ni][3];
            }
            ps0 += __shfl_xor_sync(0xffffffffu, ps0, 1);
            ps0 += __shfl_xor_sync(0xffffffffu, ps0, 2);
            ps1 += __shfl_xor_sync(0xffffffffu, ps1, 1);
            ps1 += __shfl_xor_sync(0xffffffffu, ps1, 2);
            l0 = l0 * c0 + ps0;
            l1 = l1 * c1 + ps1;
            m0 = mn0;
            m1 = mn1;
            #pragma unroll
            for (int nd = 0; nd < 16; nd++) {
                oacc[nd][0] *= c0;
                oacc[nd][1] *= c0;
                oacc[nd][2] *= c1;
                oacc[nd][3] *= c1;
            }

            #pragma unroll
            for (int j = 0; j < 4; j++) {
                uint32_t a[4];
                a[0] = f2h2(sacc[2 * j][0],     sacc[2 * j][1]);
                a[1] = f2h2(sacc[2 * j][2],     sacc[2 * j][3]);
                a[2] = f2h2(sacc[2 * j + 1][0], sacc[2 * j + 1][1]);
                a[3] = f2h2(sacc[2 * j + 1][2], sacc[2 * j + 1][3]);
                #pragma unroll
                for (int np = 0; np < 8; np++) {
                    uint32_t v[4];
                    ldm_x4_t(v, vsBase + (uint32_t)(
                        (j * 16 + (lane & 15)) * FA_SK
                        + np * 16 + ((lane >> 4) << 3)) * 2);
                    mma_f16(oacc[2 * np],     a, v);
                    mma_f16(oacc[2 * np + 1], a, v + 2);
                }
            }
        }

        if (kt + 1 < ntiles) CPA_WAIT0();
        __syncthreads();
    }

    const float inv0 = 1.f / l0;
    const float inv1 = 1.f / l1;
    __half* ob = O + ((size_t)(b * N_SEQ + qt * FA_BM + warp * 16 + (lane >> 2))) * INNER
                   + h * DHEAD + 2 * (lane & 3);
    #pragma unroll
    for (int nd = 0; nd < 16; nd++) {
        *(uint32_t*)(ob + nd * 8) = f2h2(oacc[nd][0] * inv0, oacc[nd][1] * inv0);
        *(uint32_t*)(ob + (size_t)8 * INNER + nd * 8) =
            f2h2(oacc[nd][2] * inv1, oacc[nd][3] * inv1);
    }
}

// ----------------------------------------------------------------------------
// Launch
// ----------------------------------------------------------------------------
extern "C" void kernel_launch(void* const* d_in, const int* in_sizes, int n_in,
                              void* d_out, int out_size)
{
    const float* x   = (const float*)d_in[0];
    const float* re  = (const float*)d_in[1];
    const float* g   = (const float*)d_in[2];
    const float* Wq  = (const float*)d_in[3];
    const float* Wkv = (const float*)d_in[4];
    const float* Wo  = (const float*)d_in[5];
    float* out = (float*)d_out;

    __half *xn, *qkv, *o, *wqkv, *wo;
    float *ct, *st;
    cudaGetSymbolAddress((void**)&xn,   g_xn);
    cudaGetSymbolAddress((void**)&qkv,  g_qkv);
    cudaGetSymbolAddress((void**)&o,    g_o);
    cudaGetSymbolAddress((void**)&wqkv, g_wqkv);
    cudaGetSymbolAddress((void**)&wo,   g_wo);
    cudaGetSymbolAddress((void**)&ct,   g_cos);
    cudaGetSymbolAddress((void**)&st,   g_sin);

    // 0) fused setup: weight cvt + cos/sin tables
    setup_kernel<<<(SU_TOTAL + 255) / 256, 256>>>(Wq, Wkv, Wo, re, wqkv, wo, ct, st);

    // 1) RMSNorm
    rmsnorm_kernel<<<ROWS, 256>>>(x, g, xn);

    // 2) fused qkv projection with in-epilogue RoPE on q/k block-columns
    dim3 gp(NQKV / 128, ROWS / 128);
    h16_gemm_kernel<__half, true><<<gp, 256>>>(ROWS, NQKV, DIM, xn, wqkv, qkv, ct, st);

    // 3) causal attention (BM=64, 2 CTAs/SM, cp.async KV pipeline)
    cudaFuncSetAttribute(attn_h16_kernel,
                         cudaFuncAttributeMaxDynamicSharedMemorySize, FA_SMEM);
    dim3 ga(N_SEQ / FA_BM, B * HEADS);
    attn_h16_kernel<<<ga, 128, FA_SMEM>>>(qkv, o);

    // 4) output projection
    dim3 go(DIM / 128, ROWS / 128);
    h16_gemm_kernel<float, false><<<go, 256>>>(ROWS, DIM, DIM, o, wo, out, nullptr, nullptr);
}